// round 13
// baseline (speedup 1.0000x reference)
#include <cuda_runtime.h>
#include <cuda_fp16.h>
#include <stdint.h>
#include <math.h>

typedef unsigned int u32;

#define TT 4096        // total tokens (B*T)
#define DDIM 2048
#define FDIM 2048
#define NE 8
#define TWO_F 4096
#define CAP 9216       // padded routed-row capacity: 8192 + 8*128
#define GTM 128        // CTA tile M
#define GTN 256        // CTA tile N
#define KT 64          // GEMM k-tile (halves) = 128 bytes/row
#define ROWB 144       // padded smem row stride in bytes (128 + 16)
#define STG_A (128 * ROWB)               // 18432 B per stage (A)
#define STG_BB (256 * ROWB)              // 36864 B per stage (B)
#define NS 3
#define SMEM_BYTES (NS * (STG_A + STG_BB))  // 165888

// ---------------- scratch (static device globals; no allocations) ----------------
__device__ __align__(128) __half g_xh[TT * DDIM];          // x fp16
__device__ __align__(128) __half g_xgh[CAP * DDIM];        // gathered gate-scaled tokens fp16
__device__ __align__(128) __half g_z[CAP * DDIM];          // routed-z fp16 (slot rows)
__device__ __align__(128) __half g_acth[CAP * FDIM];       // swiglu out fp16
__device__ __align__(128) __half g_sw13h[TWO_F * DDIM];    // interleaved rows
__device__ __align__(128) __half g_sw2h[DDIM * FDIM];
__device__ __align__(128) __half g_rw13h[NE * TWO_F * DDIM];  // interleaved rows per expert
__device__ __align__(128) __half g_rw2h[NE * DDIM * FDIM];
__device__ int   g_count[NE];
__device__ int   g_cursor[NE];
__device__ int   g_off[NE + 1];
__device__ int   g_tope[TT * 2];
__device__ float g_topg[TT * 2];
__device__ int   g_slot[TT * 2];

// ---------------- inline PTX helpers ----------------
__device__ __forceinline__ void cp_async16(u32 dst, const void* src) {
    asm volatile("cp.async.cg.shared.global [%0], [%1], 16;\n" :: "r"(dst), "l"(src));
}
__device__ __forceinline__ void cp_commit() {
    asm volatile("cp.async.commit_group;\n" ::: "memory");
}
__device__ __forceinline__ void cp_wait1() {
    asm volatile("cp.async.wait_group 1;\n" ::: "memory");
}
__device__ __forceinline__ void ldsm4(u32* r, u32 addr) {
    asm volatile("ldmatrix.sync.aligned.m8n8.x4.shared.b16 {%0,%1,%2,%3}, [%4];\n"
                 : "=r"(r[0]), "=r"(r[1]), "=r"(r[2]), "=r"(r[3])
                 : "r"(addr));
}
__device__ __forceinline__ void mma16816(float* d, const u32* a, u32 b0, u32 b1) {
    asm volatile(
        "mma.sync.aligned.m16n8k16.row.col.f32.f16.f16.f32 "
        "{%0,%1,%2,%3},{%4,%5,%6,%7},{%8,%9},{%0,%1,%2,%3};\n"
        : "+f"(d[0]), "+f"(d[1]), "+f"(d[2]), "+f"(d[3])
        : "r"(a[0]), "r"(a[1]), "r"(a[2]), "r"(a[3]), "r"(b0), "r"(b1));
}

// ---------------- small kernels ----------------
__global__ void zero_counts_kernel() {
    if (threadIdx.x < NE) g_count[threadIdx.x] = 0;
}

// one block per token: 8 router dots (fp32), top-2, counts
__global__ void router_kernel(const float* __restrict__ x, const float* __restrict__ rw) {
    int t = blockIdx.x;
    const float* xr = x + (long)t * DDIM;
    float acc[NE];
#pragma unroll
    for (int e = 0; e < NE; e++) acc[e] = 0.f;
    for (int d = threadIdx.x; d < DDIM; d += 256) {
        float xv = xr[d];
        const float4* rp = (const float4*)(rw + (long)d * NE);
        float4 r0 = rp[0], r1 = rp[1];
        acc[0] += xv * r0.x; acc[1] += xv * r0.y; acc[2] += xv * r0.z; acc[3] += xv * r0.w;
        acc[4] += xv * r1.x; acc[5] += xv * r1.y; acc[6] += xv * r1.z; acc[7] += xv * r1.w;
    }
    __shared__ float s[256][NE];
#pragma unroll
    for (int e = 0; e < NE; e++) s[threadIdx.x][e] = acc[e];
    __syncthreads();
    __shared__ float sc[NE];
    if (threadIdx.x < NE) {
        float v = 0.f;
        for (int i = 0; i < 256; i++) v += s[i][threadIdx.x];
        sc[threadIdx.x] = v;
    }
    __syncthreads();
    if (threadIdx.x == 0) {
        int e1 = 0; float v1 = sc[0];
        for (int e = 1; e < NE; e++) if (sc[e] > v1) { v1 = sc[e]; e1 = e; }
        int e2 = -1; float v2 = -1e30f;
        for (int e = 0; e < NE; e++) if (e != e1 && sc[e] > v2) { v2 = sc[e]; e2 = e; }
        g_tope[t * 2 + 0] = e1; g_topg[t * 2 + 0] = 1.f / (1.f + expf(-v1));
        g_tope[t * 2 + 1] = e2; g_topg[t * 2 + 1] = 1.f / (1.f + expf(-v2));
        atomicAdd(&g_count[e1], 1);
        atomicAdd(&g_count[e2], 1);
    }
}

__global__ void offsets_kernel() {
    int off = 0;
    for (int e = 0; e < NE; e++) {
        g_off[e] = off;
        g_cursor[e] = off;
        off += (g_count[e] + GTM - 1) & ~(GTM - 1);
    }
    g_off[NE] = off;
}

// zero pad rows of each expert segment in xg (64 blocks: 8 per expert)
__global__ void pad_zero_kernel() {
    int e = blockIdx.x >> 3;
    int ch = blockIdx.x & 7;
    int start = g_off[e] + g_count[e];
    int end = g_off[e + 1];
    __half2 z = __floats2half2_rn(0.f, 0.f);
    for (int r = start + ch; r < end; r += 8) {
        __half2* dh = (__half2*)(g_xgh + (long)r * DDIM);
        for (int i = threadIdx.x; i < DDIM / 2; i += 256) dh[i] = z;
    }
}

// one block per (token, slot): append gate-scaled token (fp16) to its expert segment
__global__ void gather_kernel(const float* __restrict__ x) {
    int b = blockIdx.x;
    int t = b >> 1;
    float g = g_topg[b];
    __shared__ int spos;
    if (threadIdx.x == 0) {
        spos = atomicAdd(&g_cursor[g_tope[b]], 1);
        g_slot[b] = spos;
    }
    __syncthreads();
    int pos = spos;
    const float4* xr = (const float4*)(x + (long)t * DDIM);
    __half2* dh = (__half2*)(g_xgh + (long)pos * DDIM);
    for (int i = threadIdx.x; i < DDIM / 4; i += 256) {
        float4 v = xr[i];
        dh[2 * i]     = __floats2half2_rn(v.x * g, v.y * g);
        dh[2 * i + 1] = __floats2half2_rn(v.z * g, v.w * g);
    }
}

// fp32 -> fp16 (plain)
__global__ void cvt_f16_kernel(const float4* __restrict__ in, __half2* __restrict__ out, int n4) {
    int i = blockIdx.x * blockDim.x + threadIdx.x;
    if (i >= n4) return;
    float4 v = in[i];
    out[2 * i]     = __floats2half2_rn(v.x, v.y);
    out[2 * i + 1] = __floats2half2_rn(v.z, v.w);
}

// fp32 -> fp16 with w13 row interleave: out row 2f <- in row f (w1), out row 2f+1 <- in row F+f (w3)
__global__ void cvt_i13_kernel(const float4* __restrict__ in, __half2* __restrict__ out, int n4) {
    int i = blockIdx.x * blockDim.x + threadIdx.x;
    if (i >= n4) return;
    float4 v = in[i];
    long elem = (long)i * 4;
    int row = (int)(elem >> 11);          // / DDIM
    int d   = (int)(elem & (DDIM - 1));
    int e = row >> 12;                    // / TWO_F
    int r = row & (TWO_F - 1);
    int rp = (r < FDIM) ? (2 * r) : (2 * (r - FDIM) + 1);
    long o = (((long)e * TWO_F + rp) << 11) + d;
    __half2* dst = out + (o >> 1);
    dst[0] = __floats2half2_rn(v.x, v.y);
    dst[1] = __floats2half2_rn(v.z, v.w);
}

// out[t] += z[slot0] + z[slot1]   (z fp16, row stride DDIM)
__global__ void combine_kernel(float* __restrict__ out) {
    int t = blockIdx.x;
    int s0 = g_slot[2 * t], s1 = g_slot[2 * t + 1];
    const __half2* z0 = (const __half2*)(g_z + (long)s0 * DDIM);
    const __half2* z1 = (const __half2*)(g_z + (long)s1 * DDIM);
    float2* o = (float2*)(out + (long)t * DDIM);
    for (int i = threadIdx.x; i < DDIM / 2; i += 256) {
        float2 a = o[i];
        float2 b = __half22float2(z0[i]);
        float2 c = __half22float2(z1[i]);
        a.x += b.x + c.x; a.y += b.y + c.y;
        o[i] = a;
    }
}

// ---------------- fp16 tensor-core GEMM: C = A @ B^T (128x256 tile, warp 64x64) ----------------
// EPI 0: plain fp32 store. EPI 1: fused swiglu (interleaved w13) -> fp16 at col n/2. EPI 2: plain fp16 store.
template <int EPI, bool EXPERT>
__global__ __launch_bounds__(256, 1)
void gemm_f16_kernel(const __half* __restrict__ A,
                     const __half* __restrict__ B, long bstride,
                     void* __restrict__ Cv, int ldc, int Kdim) {
    int r0 = blockIdx.y * GTM;
    int c0 = blockIdx.x * GTN;
    const __half* Bp = B;
    if (EXPERT) {
        if (r0 >= g_off[NE]) return;
        int e = 0;
        while (g_off[e + 1] <= r0) e++;
        Bp += (long)e * bstride;
    }
    extern __shared__ __half smem[];
    u32 uA = (u32)__cvta_generic_to_shared(smem);
    u32 uB = uA + NS * STG_A;

    int tid = threadIdx.x, lane = tid & 31, wid = tid >> 5;
    int wm = wid & 1, wn = wid >> 1;   // 2 x 4 warp grid, 64x64 per warp

    // global->smem: A 1024 chunks (4/thread), B 2048 chunks (8/thread)
    const char* aP[4];
    u32 aOff[4];
#pragma unroll
    for (int i = 0; i < 4; i++) {
        int c = tid + 256 * i;
        int row = c >> 3, k16 = c & 7;
        aP[i] = (const char*)(A + (long)(r0 + row) * Kdim) + k16 * 16;
        aOff[i] = (u32)(row * ROWB + k16 * 16);
    }
    const char* bPt[8];
    u32 bOff[8];
#pragma unroll
    for (int i = 0; i < 8; i++) {
        int c = tid + 256 * i;
        int row = c >> 3, k16 = c & 7;
        bPt[i] = (const char*)(Bp + (long)(c0 + row) * Kdim) + k16 * 16;
        bOff[i] = (u32)(row * ROWB + k16 * 16);
    }

    float acc[4][8][4];
#pragma unroll
    for (int i = 0; i < 4; i++)
#pragma unroll
        for (int j = 0; j < 8; j++)
#pragma unroll
            for (int k = 0; k < 4; k++) acc[i][j][k] = 0.f;

    // ldmatrix byte offsets within a stage (144-byte padded rows)
    u32 aoff = (u32)((wm * 64 + (lane & 15)) * ROWB + (lane >> 4) * 16);
    u32 boff = (u32)((wn * 64 + ((lane >> 4) << 3) + (lane & 7)) * ROWB + ((lane >> 3) & 1) * 16);

    int nk = Kdim >> 6;
    // prologue: stages 0 and 1
#pragma unroll
    for (int s = 0; s < 2; s++) {
#pragma unroll
        for (int i = 0; i < 4; i++)
            cp_async16(uA + (u32)s * STG_A + aOff[i], aP[i] + s * 128);
#pragma unroll
        for (int i = 0; i < 8; i++)
            cp_async16(uB + (u32)s * STG_BB + bOff[i], bPt[i] + s * 128);
        cp_commit();
    }

    int st = 0;
    for (int kt = 0; kt < nk; kt++) {
        cp_wait1();          // stage kt resident
        __syncthreads();
        if (kt + 2 < nk) {
            int sn = st + 2; if (sn >= NS) sn -= NS;
            long kb = (long)(kt + 2) * 128;
            u32 ao = uA + (u32)sn * STG_A;
            u32 bo = uB + (u32)sn * STG_BB;
#pragma unroll
            for (int i = 0; i < 4; i++) cp_async16(ao + aOff[i], aP[i] + kb);
#pragma unroll
            for (int i = 0; i < 8; i++) cp_async16(bo + bOff[i], bPt[i] + kb);
        }
        cp_commit();
        u32 soA = uA + (u32)st * STG_A;
        u32 soB = uB + (u32)st * STG_BB;
#pragma unroll
        for (int ks = 0; ks < 4; ks++) {
            u32 kb = (u32)ks * 32;  // 16 halves = 32 bytes
            u32 a[4][4];
#pragma unroll
            for (int mi = 0; mi < 4; mi++)
                ldsm4(a[mi], soA + aoff + (u32)mi * 16 * ROWB + kb);
#pragma unroll
            for (int np = 0; np < 4; np++) {
                u32 b[4];
                ldsm4(b, soB + boff + (u32)np * 16 * ROWB + kb);
#pragma unroll
                for (int mi = 0; mi < 4; mi++) {
                    mma16816(acc[mi][2 * np],     a[mi], b[0], b[1]);
                    mma16816(acc[mi][2 * np + 1], a[mi], b[2], b[3]);
                }
            }
        }
        if (++st == NS) st = 0;
    }

    // epilogue
    int er = lane >> 2, ec = (lane & 3) * 2;
    int m_base = r0 + wm * 64, n_base = c0 + wn * 64;
    if (EPI == 1) {
        __half* H = (__half*)Cv;
        int f0 = (c0 >> 1) + wn * 32 + (lane & 3);
#pragma unroll
        for (int mi = 0; mi < 4; mi++) {
            int rw0 = m_base + mi * 16 + er;
#pragma unroll
            for (int nt = 0; nt < 8; nt++) {
                int f = f0 + nt * 4;
                float y0 = acc[mi][nt][0], y1 = acc[mi][nt][1];
                H[(long)rw0 * ldc + f] = __float2half_rn(y0 * y1 / (1.f + __expf(-y0)));
                y0 = acc[mi][nt][2]; y1 = acc[mi][nt][3];
                H[(long)(rw0 + 8) * ldc + f] = __float2half_rn(y0 * y1 / (1.f + __expf(-y0)));
            }
        }
    } else if (EPI == 2) {
        __half* H = (__half*)Cv;
#pragma unroll
        for (int mi = 0; mi < 4; mi++) {
            int rw0 = m_base + mi * 16 + er;
#pragma unroll
            for (int nt = 0; nt < 8; nt++) {
                int n = n_base + nt * 8 + ec;
                *(__half2*)&H[(long)rw0 * ldc + n] =
                    __floats2half2_rn(acc[mi][nt][0], acc[mi][nt][1]);
                *(__half2*)&H[(long)(rw0 + 8) * ldc + n] =
                    __floats2half2_rn(acc[mi][nt][2], acc[mi][nt][3]);
            }
        }
    } else {
        float* C = (float*)Cv;
#pragma unroll
        for (int mi = 0; mi < 4; mi++) {
#pragma unroll
            for (int nt = 0; nt < 8; nt++) {
                float* p = C + (long)(m_base + mi * 16 + er) * ldc + n_base + nt * 8 + ec;
                *(float2*)p = make_float2(acc[mi][nt][0], acc[mi][nt][1]);
                *(float2*)(p + (long)8 * ldc) = make_float2(acc[mi][nt][2], acc[mi][nt][3]);
            }
        }
    }
}

// ---------------- launch ----------------
extern "C" void kernel_launch(void* const* d_in, const int* in_sizes, int n_in,
                              void* d_out, int out_size) {
    const float* x    = (const float*)d_in[0];  // (TT, D)
    const float* rw   = (const float*)d_in[1];  // (D, E)
    const float* sw13 = (const float*)d_in[2];  // (2F, D)
    const float* sw2  = (const float*)d_in[3];  // (D, F)
    const float* rw13 = (const float*)d_in[4];  // (E, 2F, D)
    const float* rw2  = (const float*)d_in[5];  // (E, D, F)
    float* out = (float*)d_out;                 // (TT, D)

    cudaFuncSetAttribute(gemm_f16_kernel<0, false>, cudaFuncAttributeMaxDynamicSharedMemorySize, SMEM_BYTES);
    cudaFuncSetAttribute(gemm_f16_kernel<1, false>, cudaFuncAttributeMaxDynamicSharedMemorySize, SMEM_BYTES);
    cudaFuncSetAttribute(gemm_f16_kernel<1, true>,  cudaFuncAttributeMaxDynamicSharedMemorySize, SMEM_BYTES);
    cudaFuncSetAttribute(gemm_f16_kernel<2, true>,  cudaFuncAttributeMaxDynamicSharedMemorySize, SMEM_BYTES);

    __half *xh, *xgh, *acth, *sw13h, *sw2h, *rw13h, *rw2h, *z;
    cudaGetSymbolAddress((void**)&xh, g_xh);
    cudaGetSymbolAddress((void**)&xgh, g_xgh);
    cudaGetSymbolAddress((void**)&acth, g_acth);
    cudaGetSymbolAddress((void**)&sw13h, g_sw13h);
    cudaGetSymbolAddress((void**)&sw2h, g_sw2h);
    cudaGetSymbolAddress((void**)&rw13h, g_rw13h);
    cudaGetSymbolAddress((void**)&rw2h, g_rw2h);
    cudaGetSymbolAddress((void**)&z, g_z);

    // routing + conversions
    zero_counts_kernel<<<1, 32>>>();
    router_kernel<<<TT, 256>>>(x, rw);
    offsets_kernel<<<1, 1>>>();
    pad_zero_kernel<<<64, 256>>>();
    gather_kernel<<<TT * 2, 256>>>(x);

    {
        int n4 = TT * DDIM / 4;
        cvt_f16_kernel<<<(n4 + 255) / 256, 256>>>((const float4*)x, (__half2*)xh, n4);
    }
    {
        int n4 = TWO_F * DDIM / 4;
        cvt_i13_kernel<<<(n4 + 255) / 256, 256>>>((const float4*)sw13, (__half2*)sw13h, n4);
    }
    {
        int n4 = DDIM * FDIM / 4;
        cvt_f16_kernel<<<(n4 + 255) / 256, 256>>>((const float4*)sw2, (__half2*)sw2h, n4);
    }
    {
        int n4 = NE * TWO_F * DDIM / 4;
        cvt_i13_kernel<<<(n4 + 255) / 256, 256>>>((const float4*)rw13, (__half2*)rw13h, n4);
    }
    {
        int n4 = NE * DDIM * FDIM / 4;
        cvt_f16_kernel<<<(n4 + 255) / 256, 256>>>((const float4*)rw2, (__half2*)rw2h, n4);
    }

    // shared expert: acth = swiglu(x @ w13'^T) [fused epi]; out = acth @ w2^T (fp32)
    gemm_f16_kernel<1, false><<<dim3(TWO_F / GTN, TT / GTM), 256, SMEM_BYTES>>>(
        xh, sw13h, 0, acth, FDIM, DDIM);
    gemm_f16_kernel<0, false><<<dim3(DDIM / GTN, TT / GTM), 256, SMEM_BYTES>>>(
        acth, sw2h, 0, out, DDIM, FDIM);

    // routed experts: acth = swiglu(xg @ w13'_e^T); z = acth @ w2_e^T (fp16); combine
    gemm_f16_kernel<1, true><<<dim3(TWO_F / GTN, CAP / GTM), 256, SMEM_BYTES>>>(
        xgh, rw13h, (long)TWO_F * DDIM, acth, FDIM, DDIM);
    gemm_f16_kernel<2, true><<<dim3(DDIM / GTN, CAP / GTM), 256, SMEM_BYTES>>>(
        acth, rw2h, (long)DDIM * FDIM, z, DDIM, FDIM);
    combine_kernel<<<TT, 256>>>(out);
}

// round 14
// speedup vs baseline: 1.0986x; 1.0986x over previous
#include <cuda_runtime.h>
#include <cuda_fp16.h>
#include <stdint.h>
#include <math.h>

typedef unsigned int u32;

#define TT 4096        // total tokens (B*T)
#define DDIM 2048
#define FDIM 2048
#define NE 8
#define TWO_F 4096
#define CAP 9216       // padded routed-row capacity: 8192 + 8*128
#define GT 128         // GEMM tile (M and N)
#define KT 64          // GEMM k-tile (halves) = 128 bytes/row
#define ROWB 144       // padded smem row stride in bytes (128 + 16)
#define STG_B (128 * ROWB)               // 18432 bytes per array per stage
#define NS 3
#define SMEM_BYTES (2 * NS * STG_B)      // A + B, 3 stages = 110592

// ---------------- scratch (static device globals; no allocations) ----------------
__device__ __align__(128) __half g_xh[TT * DDIM];          // x fp16
__device__ __align__(128) __half g_xgh[CAP * DDIM];        // gathered gate-scaled tokens fp16
__device__ __align__(128) __half g_z[CAP * DDIM];          // routed-z fp16 (slot rows)
__device__ __align__(128) __half g_acth[CAP * FDIM];       // swiglu out fp16
__device__ __align__(128) __half g_sw13h[TWO_F * DDIM];    // interleaved rows
__device__ __align__(128) __half g_sw2h[DDIM * FDIM];
__device__ __align__(128) __half g_rw13h[NE * TWO_F * DDIM];  // interleaved rows per expert
__device__ __align__(128) __half g_rw2h[NE * DDIM * FDIM];
__device__ int   g_count[NE];
__device__ int   g_cursor[NE];
__device__ int   g_off[NE + 1];
__device__ int   g_tope[TT * 2];
__device__ float g_topg[TT * 2];
__device__ int   g_slot[TT * 2];

// ---------------- inline PTX helpers ----------------
__device__ __forceinline__ void cp_async16(u32 dst, const void* src) {
    asm volatile("cp.async.cg.shared.global [%0], [%1], 16;\n" :: "r"(dst), "l"(src));
}
__device__ __forceinline__ void cp_commit() {
    asm volatile("cp.async.commit_group;\n" ::: "memory");
}
__device__ __forceinline__ void cp_wait1() {
    asm volatile("cp.async.wait_group 1;\n" ::: "memory");
}
__device__ __forceinline__ void ldsm4(u32* r, u32 addr) {
    asm volatile("ldmatrix.sync.aligned.m8n8.x4.shared.b16 {%0,%1,%2,%3}, [%4];\n"
                 : "=r"(r[0]), "=r"(r[1]), "=r"(r[2]), "=r"(r[3])
                 : "r"(addr));
}
__device__ __forceinline__ void mma16816(float* d, const u32* a, u32 b0, u32 b1) {
    asm volatile(
        "mma.sync.aligned.m16n8k16.row.col.f32.f16.f16.f32 "
        "{%0,%1,%2,%3},{%4,%5,%6,%7},{%8,%9},{%0,%1,%2,%3};\n"
        : "+f"(d[0]), "+f"(d[1]), "+f"(d[2]), "+f"(d[3])
        : "r"(a[0]), "r"(a[1]), "r"(a[2]), "r"(a[3]), "r"(b0), "r"(b1));
}

// ---------------- small kernels ----------------
__global__ void zero_counts_kernel() {
    if (threadIdx.x < NE) g_count[threadIdx.x] = 0;
}

// one block per token: 8 router dots (fp32), top-2, counts
__global__ void router_kernel(const float* __restrict__ x, const float* __restrict__ rw) {
    int t = blockIdx.x;
    const float* xr = x + (long)t * DDIM;
    float acc[NE];
#pragma unroll
    for (int e = 0; e < NE; e++) acc[e] = 0.f;
    for (int d = threadIdx.x; d < DDIM; d += 256) {
        float xv = xr[d];
        const float4* rp = (const float4*)(rw + (long)d * NE);
        float4 r0 = rp[0], r1 = rp[1];
        acc[0] += xv * r0.x; acc[1] += xv * r0.y; acc[2] += xv * r0.z; acc[3] += xv * r0.w;
        acc[4] += xv * r1.x; acc[5] += xv * r1.y; acc[6] += xv * r1.z; acc[7] += xv * r1.w;
    }
    __shared__ float s[256][NE];
#pragma unroll
    for (int e = 0; e < NE; e++) s[threadIdx.x][e] = acc[e];
    __syncthreads();
    __shared__ float sc[NE];
    if (threadIdx.x < NE) {
        float v = 0.f;
        for (int i = 0; i < 256; i++) v += s[i][threadIdx.x];
        sc[threadIdx.x] = v;
    }
    __syncthreads();
    if (threadIdx.x == 0) {
        int e1 = 0; float v1 = sc[0];
        for (int e = 1; e < NE; e++) if (sc[e] > v1) { v1 = sc[e]; e1 = e; }
        int e2 = -1; float v2 = -1e30f;
        for (int e = 0; e < NE; e++) if (e != e1 && sc[e] > v2) { v2 = sc[e]; e2 = e; }
        g_tope[t * 2 + 0] = e1; g_topg[t * 2 + 0] = 1.f / (1.f + expf(-v1));
        g_tope[t * 2 + 1] = e2; g_topg[t * 2 + 1] = 1.f / (1.f + expf(-v2));
        atomicAdd(&g_count[e1], 1);
        atomicAdd(&g_count[e2], 1);
    }
}

__global__ void offsets_kernel() {
    int off = 0;
    for (int e = 0; e < NE; e++) {
        g_off[e] = off;
        g_cursor[e] = off;
        off += (g_count[e] + GT - 1) & ~(GT - 1);
    }
    g_off[NE] = off;
}

// zero pad rows of each expert segment in xg (64 blocks: 8 per expert)
__global__ void pad_zero_kernel() {
    int e = blockIdx.x >> 3;
    int ch = blockIdx.x & 7;
    int start = g_off[e] + g_count[e];
    int end = g_off[e + 1];
    __half2 z = __floats2half2_rn(0.f, 0.f);
    for (int r = start + ch; r < end; r += 8) {
        __half2* dh = (__half2*)(g_xgh + (long)r * DDIM);
        for (int i = threadIdx.x; i < DDIM / 2; i += 256) dh[i] = z;
    }
}

// one block per (token, slot): append gate-scaled token (fp16) to its expert segment
__global__ void gather_kernel(const float* __restrict__ x) {
    int b = blockIdx.x;
    int t = b >> 1;
    float g = g_topg[b];
    __shared__ int spos;
    if (threadIdx.x == 0) {
        spos = atomicAdd(&g_cursor[g_tope[b]], 1);
        g_slot[b] = spos;
    }
    __syncthreads();
    int pos = spos;
    const float4* xr = (const float4*)(x + (long)t * DDIM);
    __half2* dh = (__half2*)(g_xgh + (long)pos * DDIM);
    for (int i = threadIdx.x; i < DDIM / 4; i += 256) {
        float4 v = xr[i];
        dh[2 * i]     = __floats2half2_rn(v.x * g, v.y * g);
        dh[2 * i + 1] = __floats2half2_rn(v.z * g, v.w * g);
    }
}

// fp32 -> fp16 (plain)
__global__ void cvt_f16_kernel(const float4* __restrict__ in, __half2* __restrict__ out, int n4) {
    int i = blockIdx.x * blockDim.x + threadIdx.x;
    if (i >= n4) return;
    float4 v = in[i];
    out[2 * i]     = __floats2half2_rn(v.x, v.y);
    out[2 * i + 1] = __floats2half2_rn(v.z, v.w);
}

// fp32 -> fp16 with w13 row interleave: out row 2f <- in row f (w1), out row 2f+1 <- in row F+f (w3)
__global__ void cvt_i13_kernel(const float4* __restrict__ in, __half2* __restrict__ out, int n4) {
    int i = blockIdx.x * blockDim.x + threadIdx.x;
    if (i >= n4) return;
    float4 v = in[i];
    long elem = (long)i * 4;
    int row = (int)(elem >> 11);          // / DDIM
    int d   = (int)(elem & (DDIM - 1));
    int e = row >> 12;                    // / TWO_F
    int r = row & (TWO_F - 1);
    int rp = (r < FDIM) ? (2 * r) : (2 * (r - FDIM) + 1);
    long o = (((long)e * TWO_F + rp) << 11) + d;
    __half2* dst = out + (o >> 1);
    dst[0] = __floats2half2_rn(v.x, v.y);
    dst[1] = __floats2half2_rn(v.z, v.w);
}

// out[t] += z[slot0] + z[slot1]   (z fp16, row stride DDIM)
__global__ void combine_kernel(float* __restrict__ out) {
    int t = blockIdx.x;
    int s0 = g_slot[2 * t], s1 = g_slot[2 * t + 1];
    const __half2* z0 = (const __half2*)(g_z + (long)s0 * DDIM);
    const __half2* z1 = (const __half2*)(g_z + (long)s1 * DDIM);
    float2* o = (float2*)(out + (long)t * DDIM);
    for (int i = threadIdx.x; i < DDIM / 2; i += 256) {
        float2 a = o[i];
        float2 b = __half22float2(z0[i]);
        float2 c = __half22float2(z1[i]);
        a.x += b.x + c.x; a.y += b.y + c.y;
        o[i] = a;
    }
}

// ---------------- fp16 tensor-core GEMM: C = A @ B^T (3-stage cp.async, KT=64) ----------------
// EPI 0: plain fp32 store. EPI 1: fused swiglu (interleaved w13) -> fp16 at col n/2. EPI 2: plain fp16 store.
template <int EPI, bool EXPERT>
__global__ __launch_bounds__(256, 2)
void gemm_f16_kernel(const __half* __restrict__ A,
                     const __half* __restrict__ B, long bstride,
                     void* __restrict__ Cv, int ldc, int Kdim) {
    int r0 = blockIdx.y * GT;
    int c0 = blockIdx.x * GT;
    const __half* Bp = B;
    if (EXPERT) {
        if (r0 >= g_off[NE]) return;
        int e = 0;
        while (g_off[e + 1] <= r0) e++;
        Bp += (long)e * bstride;
    }
    extern __shared__ __half smem[];
    u32 uA = (u32)__cvta_generic_to_shared(smem);
    u32 uB = uA + NS * STG_B;

    int tid = threadIdx.x, lane = tid & 31, wid = tid >> 5;
    int wm = wid & 3, wn = wid >> 2;

    // global->smem mapping: 1024 16B-chunks per array per stage; 4 chunks per thread
    const char* aP[4];
    const char* bP[4];
    u32 sOff[4];
#pragma unroll
    for (int i = 0; i < 4; i++) {
        int c = tid + 256 * i;
        int row = c >> 3, k16 = c & 7;
        aP[i] = (const char*)(A + (long)(r0 + row) * Kdim) + k16 * 16;
        bP[i] = (const char*)(Bp + (long)(c0 + row) * Kdim) + k16 * 16;
        sOff[i] = (u32)(row * ROWB + k16 * 16);
    }

    float acc[2][8][4];
#pragma unroll
    for (int i = 0; i < 2; i++)
#pragma unroll
        for (int j = 0; j < 8; j++)
#pragma unroll
            for (int k = 0; k < 4; k++) acc[i][j][k] = 0.f;

    // ldmatrix byte offsets within a stage (144-byte padded rows)
    u32 aoff = (u32)((wm * 32 + (lane & 15)) * ROWB + (lane >> 4) * 16);
    u32 boff = (u32)((wn * 64 + ((lane >> 4) << 3) + (lane & 7)) * ROWB + ((lane >> 3) & 1) * 16);

    int nk = Kdim >> 6;   // KT=64 stages; K=2048 -> 32
    // prologue: stages 0 and 1
#pragma unroll
    for (int s = 0; s < 2; s++) {
#pragma unroll
        for (int i = 0; i < 4; i++) {
            cp_async16(uA + (u32)s * STG_B + sOff[i], aP[i] + s * 128);
            cp_async16(uB + (u32)s * STG_B + sOff[i], bP[i] + s * 128);
        }
        cp_commit();
    }

    int st = 0;
    for (int kt = 0; kt < nk; kt++) {
        cp_wait1();          // stage kt resident
        __syncthreads();
        if (kt + 2 < nk) {
            int sn = st + 2; if (sn >= NS) sn -= NS;
            u32 ao = uA + (u32)sn * STG_B;
            u32 bo = uB + (u32)sn * STG_B;
            long kb = (long)(kt + 2) * 128;
#pragma unroll
            for (int i = 0; i < 4; i++) {
                cp_async16(ao + sOff[i], aP[i] + kb);
                cp_async16(bo + sOff[i], bP[i] + kb);
            }
        }
        cp_commit();
        u32 soA = uA + (u32)st * STG_B;
        u32 soB = uB + (u32)st * STG_B;
#pragma unroll
        for (int ks = 0; ks < 4; ks++) {
            u32 kb = (u32)ks * 32;  // 16 halves = 32 bytes
            u32 a0[4], a1[4];
            ldsm4(a0, soA + aoff + kb);
            ldsm4(a1, soA + aoff + 16 * ROWB + kb);   // warp rows +16
#pragma unroll
            for (int np = 0; np < 4; np++) {
                u32 b[4];
                ldsm4(b, soB + boff + (u32)np * 16 * ROWB + kb);
                mma16816(acc[0][2 * np],     a0, b[0], b[1]);
                mma16816(acc[0][2 * np + 1], a0, b[2], b[3]);
                mma16816(acc[1][2 * np],     a1, b[0], b[1]);
                mma16816(acc[1][2 * np + 1], a1, b[2], b[3]);
            }
        }
        if (++st == NS) st = 0;
    }

    // epilogue
    int er = lane >> 2, ec = (lane & 3) * 2;
    int m_base = r0 + wm * 32, n_base = c0 + wn * 64;
    if (EPI == 1) {
        __half* H = (__half*)Cv;
        int f0 = (c0 >> 1) + wn * 32 + (lane & 3);
#pragma unroll
        for (int mi = 0; mi < 2; mi++) {
            int rw0 = m_base + mi * 16 + er;
#pragma unroll
            for (int nt = 0; nt < 8; nt++) {
                int f = f0 + nt * 4;
                float y0 = acc[mi][nt][0], y1 = acc[mi][nt][1];
                H[(long)rw0 * ldc + f] = __float2half_rn(y0 * y1 / (1.f + __expf(-y0)));
                y0 = acc[mi][nt][2]; y1 = acc[mi][nt][3];
                H[(long)(rw0 + 8) * ldc + f] = __float2half_rn(y0 * y1 / (1.f + __expf(-y0)));
            }
        }
    } else if (EPI == 2) {
        __half* H = (__half*)Cv;
#pragma unroll
        for (int mi = 0; mi < 2; mi++) {
            int rw0 = m_base + mi * 16 + er;
#pragma unroll
            for (int nt = 0; nt < 8; nt++) {
                int n = n_base + nt * 8 + ec;
                *(__half2*)&H[(long)rw0 * ldc + n] =
                    __floats2half2_rn(acc[mi][nt][0], acc[mi][nt][1]);
                *(__half2*)&H[(long)(rw0 + 8) * ldc + n] =
                    __floats2half2_rn(acc[mi][nt][2], acc[mi][nt][3]);
            }
        }
    } else {
        float* C = (float*)Cv;
#pragma unroll
        for (int mi = 0; mi < 2; mi++) {
#pragma unroll
            for (int nt = 0; nt < 8; nt++) {
                float* p = C + (long)(m_base + mi * 16 + er) * ldc + n_base + nt * 8 + ec;
                *(float2*)p = make_float2(acc[mi][nt][0], acc[mi][nt][1]);
                *(float2*)(p + (long)8 * ldc) = make_float2(acc[mi][nt][2], acc[mi][nt][3]);
            }
        }
    }
}

// ---------------- launch ----------------
extern "C" void kernel_launch(void* const* d_in, const int* in_sizes, int n_in,
                              void* d_out, int out_size) {
    const float* x    = (const float*)d_in[0];  // (TT, D)
    const float* rw   = (const float*)d_in[1];  // (D, E)
    const float* sw13 = (const float*)d_in[2];  // (2F, D)
    const float* sw2  = (const float*)d_in[3];  // (D, F)
    const float* rw13 = (const float*)d_in[4];  // (E, 2F, D)
    const float* rw2  = (const float*)d_in[5];  // (E, D, F)
    float* out = (float*)d_out;                 // (TT, D)

    cudaFuncSetAttribute(gemm_f16_kernel<0, false>, cudaFuncAttributeMaxDynamicSharedMemorySize, SMEM_BYTES);
    cudaFuncSetAttribute(gemm_f16_kernel<1, false>, cudaFuncAttributeMaxDynamicSharedMemorySize, SMEM_BYTES);
    cudaFuncSetAttribute(gemm_f16_kernel<1, true>,  cudaFuncAttributeMaxDynamicSharedMemorySize, SMEM_BYTES);
    cudaFuncSetAttribute(gemm_f16_kernel<2, true>,  cudaFuncAttributeMaxDynamicSharedMemorySize, SMEM_BYTES);

    __half *xh, *xgh, *acth, *sw13h, *sw2h, *rw13h, *rw2h, *z;
    cudaGetSymbolAddress((void**)&xh, g_xh);
    cudaGetSymbolAddress((void**)&xgh, g_xgh);
    cudaGetSymbolAddress((void**)&acth, g_acth);
    cudaGetSymbolAddress((void**)&sw13h, g_sw13h);
    cudaGetSymbolAddress((void**)&sw2h, g_sw2h);
    cudaGetSymbolAddress((void**)&rw13h, g_rw13h);
    cudaGetSymbolAddress((void**)&rw2h, g_rw2h);
    cudaGetSymbolAddress((void**)&z, g_z);

    // routing + conversions
    zero_counts_kernel<<<1, 32>>>();
    router_kernel<<<TT, 256>>>(x, rw);
    offsets_kernel<<<1, 1>>>();
    pad_zero_kernel<<<64, 256>>>();
    gather_kernel<<<TT * 2, 256>>>(x);

    {
        int n4 = TT * DDIM / 4;
        cvt_f16_kernel<<<(n4 + 255) / 256, 256>>>((const float4*)x, (__half2*)xh, n4);
    }
    {
        int n4 = TWO_F * DDIM / 4;
        cvt_i13_kernel<<<(n4 + 255) / 256, 256>>>((const float4*)sw13, (__half2*)sw13h, n4);
    }
    {
        int n4 = DDIM * FDIM / 4;
        cvt_f16_kernel<<<(n4 + 255) / 256, 256>>>((const float4*)sw2, (__half2*)sw2h, n4);
    }
    {
        int n4 = NE * TWO_F * DDIM / 4;
        cvt_i13_kernel<<<(n4 + 255) / 256, 256>>>((const float4*)rw13, (__half2*)rw13h, n4);
    }
    {
        int n4 = NE * DDIM * FDIM / 4;
        cvt_f16_kernel<<<(n4 + 255) / 256, 256>>>((const float4*)rw2, (__half2*)rw2h, n4);
    }

    // shared expert: acth = swiglu(x @ w13'^T) [fused epi]; out = acth @ w2^T (fp32)
    gemm_f16_kernel<1, false><<<dim3(TWO_F / GT, TT / GT), 256, SMEM_BYTES>>>(
        xh, sw13h, 0, acth, FDIM, DDIM);
    gemm_f16_kernel<0, false><<<dim3(DDIM / GT, TT / GT), 256, SMEM_BYTES>>>(
        acth, sw2h, 0, out, DDIM, FDIM);

    // routed experts: acth = swiglu(xg @ w13'_e^T); z = acth @ w2_e^T (fp16); combine
    gemm_f16_kernel<1, true><<<dim3(TWO_F / GT, CAP / GT), 256, SMEM_BYTES>>>(
        xgh, rw13h, (long)TWO_F * DDIM, acth, FDIM, DDIM);
    gemm_f16_kernel<2, true><<<dim3(DDIM / GT, CAP / GT), 256, SMEM_BYTES>>>(
        acth, rw2h, (long)DDIM * FDIM, z, DDIM, FDIM);
    combine_kernel<<<TT, 256>>>(out);
}

// round 15
// speedup vs baseline: 1.1027x; 1.0037x over previous
#include <cuda_runtime.h>
#include <cuda_fp16.h>
#include <stdint.h>
#include <math.h>

typedef unsigned int u32;

#define TT 4096        // total tokens (B*T)
#define DDIM 2048
#define FDIM 2048
#define NE 8
#define TWO_F 4096
#define CAP 9216       // padded routed-row capacity: 8192 + 8*128
#define GT 128         // GEMM tile (M and N)
#define KT 64          // GEMM k-tile (halves) = 128 bytes/row
#define ROWB 144       // padded smem row stride in bytes (128 + 16)
#define STG_B (128 * ROWB)               // 18432 bytes per array per stage
#define NS 3
#define SMEM_BYTES (2 * NS * STG_B)      // A + B, 3 stages = 110592

// ---------------- scratch (static device globals; no allocations) ----------------
__device__ __align__(128) __half g_xh[TT * DDIM];          // x fp16
__device__ __align__(128) __half g_xgh[CAP * DDIM];        // gathered gate-scaled tokens fp16
__device__ __align__(128) __half g_z[CAP * DDIM];          // routed-z fp16 (slot rows)
__device__ __align__(128) __half g_acth[CAP * FDIM];       // swiglu out fp16
__device__ __align__(128) __half g_sw13h[TWO_F * DDIM];    // interleaved rows
__device__ __align__(128) __half g_sw2h[DDIM * FDIM];
__device__ __align__(128) __half g_rw13h[NE * TWO_F * DDIM];  // interleaved rows per expert
__device__ __align__(128) __half g_rw2h[NE * DDIM * FDIM];
__device__ int   g_count[NE];
__device__ int   g_cursor[NE];
__device__ int   g_off[NE + 1];
__device__ int   g_tope[TT * 2];
__device__ float g_topg[TT * 2];
__device__ int   g_slot[TT * 2];

// ---------------- inline PTX helpers ----------------
__device__ __forceinline__ void cp_async16(u32 dst, const void* src) {
    asm volatile("cp.async.cg.shared.global [%0], [%1], 16;\n" :: "r"(dst), "l"(src));
}
__device__ __forceinline__ void cp_commit() {
    asm volatile("cp.async.commit_group;\n" ::: "memory");
}
__device__ __forceinline__ void cp_wait1() {
    asm volatile("cp.async.wait_group 1;\n" ::: "memory");
}
__device__ __forceinline__ void ldsm4(u32* r, u32 addr) {
    asm volatile("ldmatrix.sync.aligned.m8n8.x4.shared.b16 {%0,%1,%2,%3}, [%4];\n"
                 : "=r"(r[0]), "=r"(r[1]), "=r"(r[2]), "=r"(r[3])
                 : "r"(addr));
}
__device__ __forceinline__ void mma16816(float* d, const u32* a, u32 b0, u32 b1) {
    asm volatile(
        "mma.sync.aligned.m16n8k16.row.col.f32.f16.f16.f32 "
        "{%0,%1,%2,%3},{%4,%5,%6,%7},{%8,%9},{%0,%1,%2,%3};\n"
        : "+f"(d[0]), "+f"(d[1]), "+f"(d[2]), "+f"(d[3])
        : "r"(a[0]), "r"(a[1]), "r"(a[2]), "r"(a[3]), "r"(b0), "r"(b1));
}

// ---------------- small kernels ----------------
__global__ void zero_counts_kernel() {
    if (threadIdx.x < NE) g_count[threadIdx.x] = 0;
}

// one block per token: 8 router dots (fp32), top-2, counts; also writes x as fp16 to g_xh
__global__ void router_kernel(const float* __restrict__ x, const float* __restrict__ rw) {
    int t = blockIdx.x;
    const float* xr = x + (long)t * DDIM;
    __half* xo = g_xh + (long)t * DDIM;
    float acc[NE];
#pragma unroll
    for (int e = 0; e < NE; e++) acc[e] = 0.f;
    for (int d = threadIdx.x; d < DDIM; d += 256) {
        float xv = xr[d];
        xo[d] = __float2half_rn(xv);
        const float4* rp = (const float4*)(rw + (long)d * NE);
        float4 r0 = rp[0], r1 = rp[1];
        acc[0] += xv * r0.x; acc[1] += xv * r0.y; acc[2] += xv * r0.z; acc[3] += xv * r0.w;
        acc[4] += xv * r1.x; acc[5] += xv * r1.y; acc[6] += xv * r1.z; acc[7] += xv * r1.w;
    }
    __shared__ float s[256][NE];
#pragma unroll
    for (int e = 0; e < NE; e++) s[threadIdx.x][e] = acc[e];
    __syncthreads();
    __shared__ float sc[NE];
    if (threadIdx.x < NE) {
        float v = 0.f;
        for (int i = 0; i < 256; i++) v += s[i][threadIdx.x];
        sc[threadIdx.x] = v;
    }
    __syncthreads();
    if (threadIdx.x == 0) {
        int e1 = 0; float v1 = sc[0];
        for (int e = 1; e < NE; e++) if (sc[e] > v1) { v1 = sc[e]; e1 = e; }
        int e2 = -1; float v2 = -1e30f;
        for (int e = 0; e < NE; e++) if (e != e1 && sc[e] > v2) { v2 = sc[e]; e2 = e; }
        g_tope[t * 2 + 0] = e1; g_topg[t * 2 + 0] = 1.f / (1.f + expf(-v1));
        g_tope[t * 2 + 1] = e2; g_topg[t * 2 + 1] = 1.f / (1.f + expf(-v2));
        atomicAdd(&g_count[e1], 1);
        atomicAdd(&g_count[e2], 1);
    }
}

__global__ void offsets_kernel() {
    int off = 0;
    for (int e = 0; e < NE; e++) {
        g_off[e] = off;
        g_cursor[e] = off;
        off += (g_count[e] + GT - 1) & ~(GT - 1);
    }
    g_off[NE] = off;
}

// zero pad rows of each expert segment in xg (64 blocks: 8 per expert)
__global__ void pad_zero_kernel() {
    int e = blockIdx.x >> 3;
    int ch = blockIdx.x & 7;
    int start = g_off[e] + g_count[e];
    int end = g_off[e + 1];
    __half2 z = __floats2half2_rn(0.f, 0.f);
    for (int r = start + ch; r < end; r += 8) {
        __half2* dh = (__half2*)(g_xgh + (long)r * DDIM);
        for (int i = threadIdx.x; i < DDIM / 2; i += 256) dh[i] = z;
    }
}

// one block per (token, slot): append gate-scaled token (fp16, from g_xh) to its expert segment
__global__ void gather_kernel() {
    int b = blockIdx.x;
    int t = b >> 1;
    float g = g_topg[b];
    __shared__ int spos;
    if (threadIdx.x == 0) {
        spos = atomicAdd(&g_cursor[g_tope[b]], 1);
        g_slot[b] = spos;
    }
    __syncthreads();
    int pos = spos;
    const __half2* xr = (const __half2*)(g_xh + (long)t * DDIM);
    __half2* dh = (__half2*)(g_xgh + (long)pos * DDIM);
    for (int i = threadIdx.x; i < DDIM / 2; i += 256) {
        float2 f = __half22float2(xr[i]);
        dh[i] = __floats2half2_rn(f.x * g, f.y * g);
    }
}

// fp32 -> fp16 (plain)
__global__ void cvt_f16_kernel(const float4* __restrict__ in, __half2* __restrict__ out, int n4) {
    int i = blockIdx.x * blockDim.x + threadIdx.x;
    if (i >= n4) return;
    float4 v = in[i];
    out[2 * i]     = __floats2half2_rn(v.x, v.y);
    out[2 * i + 1] = __floats2half2_rn(v.z, v.w);
}

// fp32 -> fp16 with w13 row interleave: out row 2f <- in row f (w1), out row 2f+1 <- in row F+f (w3)
__global__ void cvt_i13_kernel(const float4* __restrict__ in, __half2* __restrict__ out, int n4) {
    int i = blockIdx.x * blockDim.x + threadIdx.x;
    if (i >= n4) return;
    float4 v = in[i];
    long elem = (long)i * 4;
    int row = (int)(elem >> 11);          // / DDIM
    int d   = (int)(elem & (DDIM - 1));
    int e = row >> 12;                    // / TWO_F
    int r = row & (TWO_F - 1);
    int rp = (r < FDIM) ? (2 * r) : (2 * (r - FDIM) + 1);
    long o = (((long)e * TWO_F + rp) << 11) + d;
    __half2* dst = out + (o >> 1);
    dst[0] = __floats2half2_rn(v.x, v.y);
    dst[1] = __floats2half2_rn(v.z, v.w);
}

// out[t] += z[slot0] + z[slot1]   (z fp16, row stride DDIM)
__global__ void combine_kernel(float* __restrict__ out) {
    int t = blockIdx.x;
    int s0 = g_slot[2 * t], s1 = g_slot[2 * t + 1];
    const __half2* z0 = (const __half2*)(g_z + (long)s0 * DDIM);
    const __half2* z1 = (const __half2*)(g_z + (long)s1 * DDIM);
    float2* o = (float2*)(out + (long)t * DDIM);
    for (int i = threadIdx.x; i < DDIM / 2; i += 256) {
        float2 a = o[i];
        float2 b = __half22float2(z0[i]);
        float2 c = __half22float2(z1[i]);
        a.x += b.x + c.x; a.y += b.y + c.y;
        o[i] = a;
    }
}

// ---------------- fp16 tensor-core GEMM: C = A @ B^T (3-stage cp.async, KT=64) ----------------
// EPI 0: plain fp32 store. EPI 1: fused swiglu (interleaved w13) -> fp16 at col n/2. EPI 2: plain fp16 store.
template <int EPI, bool EXPERT>
__global__ __launch_bounds__(256, 2)
void gemm_f16_kernel(const __half* __restrict__ A,
                     const __half* __restrict__ B, long bstride,
                     void* __restrict__ Cv, int ldc, int Kdim) {
    int r0 = blockIdx.y * GT;
    int c0 = blockIdx.x * GT;
    const __half* Bp = B;
    if (EXPERT) {
        if (r0 >= g_off[NE]) return;
        int e = 0;
        while (g_off[e + 1] <= r0) e++;
        Bp += (long)e * bstride;
    }
    extern __shared__ __half smem[];
    u32 uA = (u32)__cvta_generic_to_shared(smem);
    u32 uB = uA + NS * STG_B;

    int tid = threadIdx.x, lane = tid & 31, wid = tid >> 5;
    int wm = wid & 3, wn = wid >> 2;

    // global->smem mapping: 1024 16B-chunks per array per stage; 4 chunks per thread
    const char* aP[4];
    const char* bP[4];
    u32 sOff[4];
#pragma unroll
    for (int i = 0; i < 4; i++) {
        int c = tid + 256 * i;
        int row = c >> 3, k16 = c & 7;
        aP[i] = (const char*)(A + (long)(r0 + row) * Kdim) + k16 * 16;
        bP[i] = (const char*)(Bp + (long)(c0 + row) * Kdim) + k16 * 16;
        sOff[i] = (u32)(row * ROWB + k16 * 16);
    }

    float acc[2][8][4];
#pragma unroll
    for (int i = 0; i < 2; i++)
#pragma unroll
        for (int j = 0; j < 8; j++)
#pragma unroll
            for (int k = 0; k < 4; k++) acc[i][j][k] = 0.f;

    // ldmatrix byte offsets within a stage (144-byte padded rows)
    u32 aoff = (u32)((wm * 32 + (lane & 15)) * ROWB + (lane >> 4) * 16);
    u32 boff = (u32)((wn * 64 + ((lane >> 4) << 3) + (lane & 7)) * ROWB + ((lane >> 3) & 1) * 16);

    int nk = Kdim >> 6;   // KT=64 stages; K=2048 -> 32
    // prologue: stages 0 and 1
#pragma unroll
    for (int s = 0; s < 2; s++) {
#pragma unroll
        for (int i = 0; i < 4; i++) {
            cp_async16(uA + (u32)s * STG_B + sOff[i], aP[i] + s * 128);
            cp_async16(uB + (u32)s * STG_B + sOff[i], bP[i] + s * 128);
        }
        cp_commit();
    }

    int st = 0;
    for (int kt = 0; kt < nk; kt++) {
        cp_wait1();          // stage kt resident
        __syncthreads();
        if (kt + 2 < nk) {
            int sn = st + 2; if (sn >= NS) sn -= NS;
            u32 ao = uA + (u32)sn * STG_B;
            u32 bo = uB + (u32)sn * STG_B;
            long kb = (long)(kt + 2) * 128;
#pragma unroll
            for (int i = 0; i < 4; i++) {
                cp_async16(ao + sOff[i], aP[i] + kb);
                cp_async16(bo + sOff[i], bP[i] + kb);
            }
        }
        cp_commit();
        u32 soA = uA + (u32)st * STG_B;
        u32 soB = uB + (u32)st * STG_B;
#pragma unroll
        for (int ks = 0; ks < 4; ks++) {
            u32 kb = (u32)ks * 32;  // 16 halves = 32 bytes
            u32 a0[4], a1[4];
            ldsm4(a0, soA + aoff + kb);
            ldsm4(a1, soA + aoff + 16 * ROWB + kb);   // warp rows +16
#pragma unroll
            for (int np = 0; np < 4; np++) {
                u32 b[4];
                ldsm4(b, soB + boff + (u32)np * 16 * ROWB + kb);
                mma16816(acc[0][2 * np],     a0, b[0], b[1]);
                mma16816(acc[0][2 * np + 1], a0, b[2], b[3]);
                mma16816(acc[1][2 * np],     a1, b[0], b[1]);
                mma16816(acc[1][2 * np + 1], a1, b[2], b[3]);
            }
        }
        if (++st == NS) st = 0;
    }

    // epilogue
    int er = lane >> 2, ec = (lane & 3) * 2;
    int m_base = r0 + wm * 32, n_base = c0 + wn * 64;
    if (EPI == 1) {
        __half* H = (__half*)Cv;
        int f0 = (c0 >> 1) + wn * 32 + (lane & 3);
#pragma unroll
        for (int mi = 0; mi < 2; mi++) {
            int rw0 = m_base + mi * 16 + er;
#pragma unroll
            for (int nt = 0; nt < 8; nt++) {
                int f = f0 + nt * 4;
                float y0 = acc[mi][nt][0], y1 = acc[mi][nt][1];
                H[(long)rw0 * ldc + f] = __float2half_rn(y0 * y1 / (1.f + __expf(-y0)));
                y0 = acc[mi][nt][2]; y1 = acc[mi][nt][3];
                H[(long)(rw0 + 8) * ldc + f] = __float2half_rn(y0 * y1 / (1.f + __expf(-y0)));
            }
        }
    } else if (EPI == 2) {
        __half* H = (__half*)Cv;
#pragma unroll
        for (int mi = 0; mi < 2; mi++) {
            int rw0 = m_base + mi * 16 + er;
#pragma unroll
            for (int nt = 0; nt < 8; nt++) {
                int n = n_base + nt * 8 + ec;
                *(__half2*)&H[(long)rw0 * ldc + n] =
                    __floats2half2_rn(acc[mi][nt][0], acc[mi][nt][1]);
                *(__half2*)&H[(long)(rw0 + 8) * ldc + n] =
                    __floats2half2_rn(acc[mi][nt][2], acc[mi][nt][3]);
            }
        }
    } else {
        float* C = (float*)Cv;
#pragma unroll
        for (int mi = 0; mi < 2; mi++) {
#pragma unroll
            for (int nt = 0; nt < 8; nt++) {
                float* p = C + (long)(m_base + mi * 16 + er) * ldc + n_base + nt * 8 + ec;
                *(float2*)p = make_float2(acc[mi][nt][0], acc[mi][nt][1]);
                *(float2*)(p + (long)8 * ldc) = make_float2(acc[mi][nt][2], acc[mi][nt][3]);
            }
        }
    }
}

// ---------------- launch ----------------
extern "C" void kernel_launch(void* const* d_in, const int* in_sizes, int n_in,
                              void* d_out, int out_size) {
    const float* x    = (const float*)d_in[0];  // (TT, D)
    const float* rw   = (const float*)d_in[1];  // (D, E)
    const float* sw13 = (const float*)d_in[2];  // (2F, D)
    const float* sw2  = (const float*)d_in[3];  // (D, F)
    const float* rw13 = (const float*)d_in[4];  // (E, 2F, D)
    const float* rw2  = (const float*)d_in[5];  // (E, D, F)
    float* out = (float*)d_out;                 // (TT, D)

    // one-time host-side resources (no device memory involved)
    static cudaStream_t s2 = 0;
    static cudaEvent_t evFork = 0, evJoin = 0;
    if (s2 == 0) {
        cudaStreamCreateWithFlags(&s2, cudaStreamNonBlocking);
        cudaEventCreateWithFlags(&evFork, cudaEventDisableTiming);
        cudaEventCreateWithFlags(&evJoin, cudaEventDisableTiming);
    }

    cudaFuncSetAttribute(gemm_f16_kernel<0, false>, cudaFuncAttributeMaxDynamicSharedMemorySize, SMEM_BYTES);
    cudaFuncSetAttribute(gemm_f16_kernel<1, false>, cudaFuncAttributeMaxDynamicSharedMemorySize, SMEM_BYTES);
    cudaFuncSetAttribute(gemm_f16_kernel<1, true>,  cudaFuncAttributeMaxDynamicSharedMemorySize, SMEM_BYTES);
    cudaFuncSetAttribute(gemm_f16_kernel<2, true>,  cudaFuncAttributeMaxDynamicSharedMemorySize, SMEM_BYTES);

    __half *xh, *xgh, *acth, *sw13h, *sw2h, *rw13h, *rw2h, *z;
    cudaGetSymbolAddress((void**)&xh, g_xh);
    cudaGetSymbolAddress((void**)&xgh, g_xgh);
    cudaGetSymbolAddress((void**)&acth, g_acth);
    cudaGetSymbolAddress((void**)&sw13h, g_sw13h);
    cudaGetSymbolAddress((void**)&sw2h, g_sw2h);
    cudaGetSymbolAddress((void**)&rw13h, g_rw13h);
    cudaGetSymbolAddress((void**)&rw2h, g_rw2h);
    cudaGetSymbolAddress((void**)&z, g_z);

    // fork: routed-weight conversions on s2, overlapping the shared-expert chain on stream 0
    cudaEventRecord(evFork, 0);
    cudaStreamWaitEvent(s2, evFork, 0);
    {
        int n4 = NE * TWO_F * DDIM / 4;
        cvt_i13_kernel<<<(n4 + 255) / 256, 256, 0, s2>>>((const float4*)rw13, (__half2*)rw13h, n4);
    }
    {
        int n4 = NE * DDIM * FDIM / 4;
        cvt_f16_kernel<<<(n4 + 255) / 256, 256, 0, s2>>>((const float4*)rw2, (__half2*)rw2h, n4);
    }
    cudaEventRecord(evJoin, s2);

    // stream 0: shared-expert weights + routing
    {
        int n4 = TWO_F * DDIM / 4;
        cvt_i13_kernel<<<(n4 + 255) / 256, 256>>>((const float4*)sw13, (__half2*)sw13h, n4);
    }
    {
        int n4 = DDIM * FDIM / 4;
        cvt_f16_kernel<<<(n4 + 255) / 256, 256>>>((const float4*)sw2, (__half2*)sw2h, n4);
    }
    zero_counts_kernel<<<1, 32>>>();
    router_kernel<<<TT, 256>>>(x, rw);   // also writes g_xh (fp16)
    offsets_kernel<<<1, 1>>>();
    pad_zero_kernel<<<64, 256>>>();
    gather_kernel<<<TT * 2, 256>>>();    // reads g_xh

    // shared expert: acth = swiglu(x @ w13'^T) [fused epi]; out = acth @ w2^T (fp32)
    gemm_f16_kernel<1, false><<<dim3(TWO_F / GT, TT / GT), 256, SMEM_BYTES>>>(
        xh, sw13h, 0, acth, FDIM, DDIM);
    gemm_f16_kernel<0, false><<<dim3(DDIM / GT, TT / GT), 256, SMEM_BYTES>>>(
        acth, sw2h, 0, out, DDIM, FDIM);

    // join: routed weights ready
    cudaStreamWaitEvent(0, evJoin, 0);

    // routed experts: acth = swiglu(xg @ w13'_e^T); z = acth @ w2_e^T (fp16); combine
    gemm_f16_kernel<1, true><<<dim3(TWO_F / GT, CAP / GT), 256, SMEM_BYTES>>>(
        xgh, rw13h, (long)TWO_F * DDIM, acth, FDIM, DDIM);
    gemm_f16_kernel<2, true><<<dim3(DDIM / GT, CAP / GT), 256, SMEM_BYTES>>>(
        acth, rw2h, (long)DDIM * FDIM, z, DDIM, FDIM);
    combine_kernel<<<TT, 256>>>(out);
}

// round 16
// speedup vs baseline: 1.1822x; 1.0721x over previous
#include <cuda_runtime.h>
#include <cuda_fp16.h>
#include <stdint.h>
#include <math.h>

typedef unsigned int u32;

#define TT 4096        // total tokens (B*T)
#define DDIM 2048
#define FDIM 2048
#define NE 8
#define TWO_F 4096
#define CAP 9216       // padded routed-row capacity: 8192 + 8*128
#define GT 128         // GEMM tile (M and N)
#define KT 64          // GEMM k-tile (halves) = 128 bytes/row
#define ROWB 144       // padded smem row stride in bytes (128 + 16)
#define STG_B (128 * ROWB)               // 18432 bytes per array per stage
#define NS 3
#define SMEM_BYTES (2 * NS * STG_B)      // A + B, 3 stages = 110592

// ---------------- scratch (static device globals; no allocations) ----------------
__device__ __align__(128) __half g_xh[TT * DDIM];          // x fp16
__device__ __align__(128) __half g_xgh[CAP * DDIM];        // gathered gate-scaled tokens fp16
__device__ __align__(128) __half g_z[CAP * DDIM];          // routed-z fp16 (slot rows)
__device__ __align__(128) __half g_acth[CAP * FDIM];       // routed swiglu out fp16
__device__ __align__(128) __half g_acts[TT * FDIM];        // shared swiglu out fp16
__device__ __align__(128) __half g_sw13h[TWO_F * DDIM];    // interleaved rows
__device__ __align__(128) __half g_sw2h[DDIM * FDIM];
__device__ __align__(128) __half g_rw13h[NE * TWO_F * DDIM];  // interleaved rows per expert
__device__ __align__(128) __half g_rw2h[NE * DDIM * FDIM];
__device__ int   g_count[NE];
__device__ int   g_cursor[NE];
__device__ int   g_off[NE + 1];
__device__ int   g_tope[TT * 2];
__device__ float g_topg[TT * 2];
__device__ int   g_slot[TT * 2];

// ---------------- inline PTX helpers ----------------
__device__ __forceinline__ void cp_async16(u32 dst, const void* src) {
    asm volatile("cp.async.cg.shared.global [%0], [%1], 16;\n" :: "r"(dst), "l"(src));
}
__device__ __forceinline__ void cp_commit() {
    asm volatile("cp.async.commit_group;\n" ::: "memory");
}
__device__ __forceinline__ void cp_wait1() {
    asm volatile("cp.async.wait_group 1;\n" ::: "memory");
}
__device__ __forceinline__ void ldsm4(u32* r, u32 addr) {
    asm volatile("ldmatrix.sync.aligned.m8n8.x4.shared.b16 {%0,%1,%2,%3}, [%4];\n"
                 : "=r"(r[0]), "=r"(r[1]), "=r"(r[2]), "=r"(r[3])
                 : "r"(addr));
}
__device__ __forceinline__ void mma16816(float* d, const u32* a, u32 b0, u32 b1) {
    asm volatile(
        "mma.sync.aligned.m16n8k16.row.col.f32.f16.f16.f32 "
        "{%0,%1,%2,%3},{%4,%5,%6,%7},{%8,%9},{%0,%1,%2,%3};\n"
        : "+f"(d[0]), "+f"(d[1]), "+f"(d[2]), "+f"(d[3])
        : "r"(a[0]), "r"(a[1]), "r"(a[2]), "r"(a[3]), "r"(b0), "r"(b1));
}

// ---------------- small kernels ----------------
__global__ void zero_counts_kernel() {
    if (threadIdx.x < NE) g_count[threadIdx.x] = 0;
}

// one block per token: 8 router dots (fp32), top-2, counts; also writes x as fp16 to g_xh
__global__ void router_kernel(const float* __restrict__ x, const float* __restrict__ rw) {
    int t = blockIdx.x;
    const float* xr = x + (long)t * DDIM;
    __half* xo = g_xh + (long)t * DDIM;
    float acc[NE];
#pragma unroll
    for (int e = 0; e < NE; e++) acc[e] = 0.f;
    for (int d = threadIdx.x; d < DDIM; d += 256) {
        float xv = xr[d];
        xo[d] = __float2half_rn(xv);
        const float4* rp = (const float4*)(rw + (long)d * NE);
        float4 r0 = rp[0], r1 = rp[1];
        acc[0] += xv * r0.x; acc[1] += xv * r0.y; acc[2] += xv * r0.z; acc[3] += xv * r0.w;
        acc[4] += xv * r1.x; acc[5] += xv * r1.y; acc[6] += xv * r1.z; acc[7] += xv * r1.w;
    }
    __shared__ float s[256][NE];
#pragma unroll
    for (int e = 0; e < NE; e++) s[threadIdx.x][e] = acc[e];
    __syncthreads();
    __shared__ float sc[NE];
    if (threadIdx.x < NE) {
        float v = 0.f;
        for (int i = 0; i < 256; i++) v += s[i][threadIdx.x];
        sc[threadIdx.x] = v;
    }
    __syncthreads();
    if (threadIdx.x == 0) {
        int e1 = 0; float v1 = sc[0];
        for (int e = 1; e < NE; e++) if (sc[e] > v1) { v1 = sc[e]; e1 = e; }
        int e2 = -1; float v2 = -1e30f;
        for (int e = 0; e < NE; e++) if (e != e1 && sc[e] > v2) { v2 = sc[e]; e2 = e; }
        g_tope[t * 2 + 0] = e1; g_topg[t * 2 + 0] = 1.f / (1.f + expf(-v1));
        g_tope[t * 2 + 1] = e2; g_topg[t * 2 + 1] = 1.f / (1.f + expf(-v2));
        atomicAdd(&g_count[e1], 1);
        atomicAdd(&g_count[e2], 1);
    }
}

__global__ void offsets_kernel() {
    int off = 0;
    for (int e = 0; e < NE; e++) {
        g_off[e] = off;
        g_cursor[e] = off;
        off += (g_count[e] + GT - 1) & ~(GT - 1);
    }
    g_off[NE] = off;
}

// zero pad rows of each expert segment in xg (64 blocks: 8 per expert)
__global__ void pad_zero_kernel() {
    int e = blockIdx.x >> 3;
    int ch = blockIdx.x & 7;
    int start = g_off[e] + g_count[e];
    int end = g_off[e + 1];
    __half2 z = __floats2half2_rn(0.f, 0.f);
    for (int r = start + ch; r < end; r += 8) {
        __half2* dh = (__half2*)(g_xgh + (long)r * DDIM);
        for (int i = threadIdx.x; i < DDIM / 2; i += 256) dh[i] = z;
    }
}

// one block per (token, slot): append gate-scaled token (fp16, from g_xh) to its expert segment
__global__ void gather_kernel() {
    int b = blockIdx.x;
    int t = b >> 1;
    float g = g_topg[b];
    __shared__ int spos;
    if (threadIdx.x == 0) {
        spos = atomicAdd(&g_cursor[g_tope[b]], 1);
        g_slot[b] = spos;
    }
    __syncthreads();
    int pos = spos;
    const __half2* xr = (const __half2*)(g_xh + (long)t * DDIM);
    __half2* dh = (__half2*)(g_xgh + (long)pos * DDIM);
    for (int i = threadIdx.x; i < DDIM / 2; i += 256) {
        float2 f = __half22float2(xr[i]);
        dh[i] = __floats2half2_rn(f.x * g, f.y * g);
    }
}

// fp32 -> fp16 (plain)
__global__ void cvt_f16_kernel(const float4* __restrict__ in, __half2* __restrict__ out, int n4) {
    int i = blockIdx.x * blockDim.x + threadIdx.x;
    if (i >= n4) return;
    float4 v = in[i];
    out[2 * i]     = __floats2half2_rn(v.x, v.y);
    out[2 * i + 1] = __floats2half2_rn(v.z, v.w);
}

// fp32 -> fp16 with w13 row interleave: out row 2f <- in row f (w1), out row 2f+1 <- in row F+f (w3)
__global__ void cvt_i13_kernel(const float4* __restrict__ in, __half2* __restrict__ out, int n4) {
    int i = blockIdx.x * blockDim.x + threadIdx.x;
    if (i >= n4) return;
    float4 v = in[i];
    long elem = (long)i * 4;
    int row = (int)(elem >> 11);          // / DDIM
    int d   = (int)(elem & (DDIM - 1));
    int e = row >> 12;                    // / TWO_F
    int r = row & (TWO_F - 1);
    int rp = (r < FDIM) ? (2 * r) : (2 * (r - FDIM) + 1);
    long o = (((long)e * TWO_F + rp) << 11) + d;
    __half2* dst = out + (o >> 1);
    dst[0] = __floats2half2_rn(v.x, v.y);
    dst[1] = __floats2half2_rn(v.z, v.w);
}

// out[t] += z[slot0] + z[slot1]   (z fp16, row stride DDIM)
__global__ void combine_kernel(float* __restrict__ out) {
    int t = blockIdx.x;
    int s0 = g_slot[2 * t], s1 = g_slot[2 * t + 1];
    const __half2* z0 = (const __half2*)(g_z + (long)s0 * DDIM);
    const __half2* z1 = (const __half2*)(g_z + (long)s1 * DDIM);
    float2* o = (float2*)(out + (long)t * DDIM);
    for (int i = threadIdx.x; i < DDIM / 2; i += 256) {
        float2 a = o[i];
        float2 b = __half22float2(z0[i]);
        float2 c = __half22float2(z1[i]);
        a.x += b.x + c.x; a.y += b.y + c.y;
        o[i] = a;
    }
}

// ---------------- fp16 tensor-core GEMM: C = A @ B^T (3-stage cp.async, KT=64) ----------------
// EPI 0: plain fp32 store. EPI 1: fused swiglu (interleaved w13) -> fp16 at col n/2. EPI 2: plain fp16 store.
template <int EPI, bool EXPERT>
__global__ __launch_bounds__(256, 2)
void gemm_f16_kernel(const __half* __restrict__ A,
                     const __half* __restrict__ B, long bstride,
                     void* __restrict__ Cv, int ldc, int Kdim) {
    int r0 = blockIdx.y * GT;
    int c0 = blockIdx.x * GT;
    const __half* Bp = B;
    if (EXPERT) {
        if (r0 >= g_off[NE]) return;
        int e = 0;
        while (g_off[e + 1] <= r0) e++;
        Bp += (long)e * bstride;
    }
    extern __shared__ __half smem[];
    u32 uA = (u32)__cvta_generic_to_shared(smem);
    u32 uB = uA + NS * STG_B;

    int tid = threadIdx.x, lane = tid & 31, wid = tid >> 5;
    int wm = wid & 3, wn = wid >> 2;

    // global->smem mapping: 1024 16B-chunks per array per stage; 4 chunks per thread
    const char* aP[4];
    const char* bP[4];
    u32 sOff[4];
#pragma unroll
    for (int i = 0; i < 4; i++) {
        int c = tid + 256 * i;
        int row = c >> 3, k16 = c & 7;
        aP[i] = (const char*)(A + (long)(r0 + row) * Kdim) + k16 * 16;
        bP[i] = (const char*)(Bp + (long)(c0 + row) * Kdim) + k16 * 16;
        sOff[i] = (u32)(row * ROWB + k16 * 16);
    }

    float acc[2][8][4];
#pragma unroll
    for (int i = 0; i < 2; i++)
#pragma unroll
        for (int j = 0; j < 8; j++)
#pragma unroll
            for (int k = 0; k < 4; k++) acc[i][j][k] = 0.f;

    // ldmatrix byte offsets within a stage (144-byte padded rows)
    u32 aoff = (u32)((wm * 32 + (lane & 15)) * ROWB + (lane >> 4) * 16);
    u32 boff = (u32)((wn * 64 + ((lane >> 4) << 3) + (lane & 7)) * ROWB + ((lane >> 3) & 1) * 16);

    int nk = Kdim >> 6;   // KT=64 stages; K=2048 -> 32
    // prologue: stages 0 and 1
#pragma unroll
    for (int s = 0; s < 2; s++) {
#pragma unroll
        for (int i = 0; i < 4; i++) {
            cp_async16(uA + (u32)s * STG_B + sOff[i], aP[i] + s * 128);
            cp_async16(uB + (u32)s * STG_B + sOff[i], bP[i] + s * 128);
        }
        cp_commit();
    }

    int st = 0;
    for (int kt = 0; kt < nk; kt++) {
        cp_wait1();          // stage kt resident
        __syncthreads();
        if (kt + 2 < nk) {
            int sn = st + 2; if (sn >= NS) sn -= NS;
            u32 ao = uA + (u32)sn * STG_B;
            u32 bo = uB + (u32)sn * STG_B;
            long kb = (long)(kt + 2) * 128;
#pragma unroll
            for (int i = 0; i < 4; i++) {
                cp_async16(ao + sOff[i], aP[i] + kb);
                cp_async16(bo + sOff[i], bP[i] + kb);
            }
        }
        cp_commit();
        u32 soA = uA + (u32)st * STG_B;
        u32 soB = uB + (u32)st * STG_B;
#pragma unroll
        for (int ks = 0; ks < 4; ks++) {
            u32 kb = (u32)ks * 32;  // 16 halves = 32 bytes
            u32 a0[4], a1[4];
            ldsm4(a0, soA + aoff + kb);
            ldsm4(a1, soA + aoff + 16 * ROWB + kb);   // warp rows +16
#pragma unroll
            for (int np = 0; np < 4; np++) {
                u32 b[4];
                ldsm4(b, soB + boff + (u32)np * 16 * ROWB + kb);
                mma16816(acc[0][2 * np],     a0, b[0], b[1]);
                mma16816(acc[0][2 * np + 1], a0, b[2], b[3]);
                mma16816(acc[1][2 * np],     a1, b[0], b[1]);
                mma16816(acc[1][2 * np + 1], a1, b[2], b[3]);
            }
        }
        if (++st == NS) st = 0;
    }

    // epilogue
    int er = lane >> 2, ec = (lane & 3) * 2;
    int m_base = r0 + wm * 32, n_base = c0 + wn * 64;
    if (EPI == 1) {
        __half* H = (__half*)Cv;
        int f0 = (c0 >> 1) + wn * 32 + (lane & 3);
#pragma unroll
        for (int mi = 0; mi < 2; mi++) {
            int rw0 = m_base + mi * 16 + er;
#pragma unroll
            for (int nt = 0; nt < 8; nt++) {
                int f = f0 + nt * 4;
                float y0 = acc[mi][nt][0], y1 = acc[mi][nt][1];
                H[(long)rw0 * ldc + f] = __float2half_rn(y0 * y1 / (1.f + __expf(-y0)));
                y0 = acc[mi][nt][2]; y1 = acc[mi][nt][3];
                H[(long)(rw0 + 8) * ldc + f] = __float2half_rn(y0 * y1 / (1.f + __expf(-y0)));
            }
        }
    } else if (EPI == 2) {
        __half* H = (__half*)Cv;
#pragma unroll
        for (int mi = 0; mi < 2; mi++) {
            int rw0 = m_base + mi * 16 + er;
#pragma unroll
            for (int nt = 0; nt < 8; nt++) {
                int n = n_base + nt * 8 + ec;
                *(__half2*)&H[(long)rw0 * ldc + n] =
                    __floats2half2_rn(acc[mi][nt][0], acc[mi][nt][1]);
                *(__half2*)&H[(long)(rw0 + 8) * ldc + n] =
                    __floats2half2_rn(acc[mi][nt][2], acc[mi][nt][3]);
            }
        }
    } else {
        float* C = (float*)Cv;
#pragma unroll
        for (int mi = 0; mi < 2; mi++) {
#pragma unroll
            for (int nt = 0; nt < 8; nt++) {
                float* p = C + (long)(m_base + mi * 16 + er) * ldc + n_base + nt * 8 + ec;
                *(float2*)p = make_float2(acc[mi][nt][0], acc[mi][nt][1]);
                *(float2*)(p + (long)8 * ldc) = make_float2(acc[mi][nt][2], acc[mi][nt][3]);
            }
        }
    }
}

// ---------------- launch ----------------
extern "C" void kernel_launch(void* const* d_in, const int* in_sizes, int n_in,
                              void* d_out, int out_size) {
    const float* x    = (const float*)d_in[0];  // (TT, D)
    const float* rw   = (const float*)d_in[1];  // (D, E)
    const float* sw13 = (const float*)d_in[2];  // (2F, D)
    const float* sw2  = (const float*)d_in[3];  // (D, F)
    const float* rw13 = (const float*)d_in[4];  // (E, 2F, D)
    const float* rw2  = (const float*)d_in[5];  // (E, D, F)
    float* out = (float*)d_out;                 // (TT, D)

    // one-time host-side resources (no device memory involved)
    static cudaStream_t s2 = 0;
    static cudaEvent_t evFork = 0, evGather = 0, evJoin = 0;
    if (s2 == 0) {
        cudaStreamCreateWithFlags(&s2, cudaStreamNonBlocking);
        cudaEventCreateWithFlags(&evFork, cudaEventDisableTiming);
        cudaEventCreateWithFlags(&evGather, cudaEventDisableTiming);
        cudaEventCreateWithFlags(&evJoin, cudaEventDisableTiming);
    }

    cudaFuncSetAttribute(gemm_f16_kernel<0, false>, cudaFuncAttributeMaxDynamicSharedMemorySize, SMEM_BYTES);
    cudaFuncSetAttribute(gemm_f16_kernel<1, false>, cudaFuncAttributeMaxDynamicSharedMemorySize, SMEM_BYTES);
    cudaFuncSetAttribute(gemm_f16_kernel<1, true>,  cudaFuncAttributeMaxDynamicSharedMemorySize, SMEM_BYTES);
    cudaFuncSetAttribute(gemm_f16_kernel<2, true>,  cudaFuncAttributeMaxDynamicSharedMemorySize, SMEM_BYTES);

    __half *xh, *xgh, *acth, *acts, *sw13h, *sw2h, *rw13h, *rw2h, *z;
    cudaGetSymbolAddress((void**)&xh, g_xh);
    cudaGetSymbolAddress((void**)&xgh, g_xgh);
    cudaGetSymbolAddress((void**)&acth, g_acth);
    cudaGetSymbolAddress((void**)&acts, g_acts);
    cudaGetSymbolAddress((void**)&sw13h, g_sw13h);
    cudaGetSymbolAddress((void**)&sw2h, g_sw2h);
    cudaGetSymbolAddress((void**)&rw13h, g_rw13h);
    cudaGetSymbolAddress((void**)&rw2h, g_rw2h);
    cudaGetSymbolAddress((void**)&z, g_z);

    // fork: routed-weight conversions start immediately on s2
    cudaEventRecord(evFork, 0);
    cudaStreamWaitEvent(s2, evFork, 0);
    {
        int n4 = NE * TWO_F * DDIM / 4;
        cvt_i13_kernel<<<(n4 + 255) / 256, 256, 0, s2>>>((const float4*)rw13, (__half2*)rw13h, n4);
    }
    {
        int n4 = NE * DDIM * FDIM / 4;
        cvt_f16_kernel<<<(n4 + 255) / 256, 256, 0, s2>>>((const float4*)rw2, (__half2*)rw2h, n4);
    }

    // stream 0: shared-expert weights + routing
    {
        int n4 = TWO_F * DDIM / 4;
        cvt_i13_kernel<<<(n4 + 255) / 256, 256>>>((const float4*)sw13, (__half2*)sw13h, n4);
    }
    {
        int n4 = DDIM * FDIM / 4;
        cvt_f16_kernel<<<(n4 + 255) / 256, 256>>>((const float4*)sw2, (__half2*)sw2h, n4);
    }
    zero_counts_kernel<<<1, 32>>>();
    router_kernel<<<TT, 256>>>(x, rw);   // also writes g_xh (fp16)
    offsets_kernel<<<1, 1>>>();
    pad_zero_kernel<<<64, 256>>>();
    gather_kernel<<<TT * 2, 256>>>();    // reads g_xh
    cudaEventRecord(evGather, 0);

    // s2: routed chain (waits for gather + its own weight conversions)
    cudaStreamWaitEvent(s2, evGather, 0);
    gemm_f16_kernel<1, true><<<dim3(TWO_F / GT, CAP / GT), 256, SMEM_BYTES, s2>>>(
        xgh, rw13h, (long)TWO_F * DDIM, acth, FDIM, DDIM);
    gemm_f16_kernel<2, true><<<dim3(DDIM / GT, CAP / GT), 256, SMEM_BYTES, s2>>>(
        acth, rw2h, (long)DDIM * FDIM, z, DDIM, FDIM);
    cudaEventRecord(evJoin, s2);

    // stream 0: shared chain (concurrent with routed chain)
    gemm_f16_kernel<1, false><<<dim3(TWO_F / GT, TT / GT), 256, SMEM_BYTES>>>(
        xh, sw13h, 0, acts, FDIM, DDIM);
    gemm_f16_kernel<0, false><<<dim3(DDIM / GT, TT / GT), 256, SMEM_BYTES>>>(
        acts, sw2h, 0, out, DDIM, FDIM);

    // join: routed z ready, then combine
    cudaStreamWaitEvent(0, evJoin, 0);
    combine_kernel<<<TT, 256>>>(out);
}